// round 8
// baseline (speedup 1.0000x reference)
#include <cuda_runtime.h>
#include <math.h>

#define D 128
#define MAXN 50000
#define MAXE 400000

// ---------------- scratch (static __device__, no allocation) ----------------
// __device__ globals are zero-initialized at module load; k_tail re-zeros
// g_deg/g_bcnt at the end of every call so each graph replay sees clean state.
__device__ float g_h[MAXN * D];          // per-node attention-weighted message
__device__ int   g_deg[MAXN];
__device__ int   g_csroff[MAXN + 1];
__device__ int   g_cursor[MAXN];
__device__ int   g_eid[MAXE];
__device__ int   g_perm[MAXN];           // nodes sorted by cat
__device__ int   g_bcnt[3];
__device__ int   g_boff[4];
__device__ int   g_bcur[3];
// packed weight matrices: pair-of-k-rows layout, Wp[m][kp*D + c] = (W[2kp][c], W[2kp+1][c])
// m: 0=Wr0 1=Wr1 2=Wr2 3=WgTop 4=WgBot 5=G0 6=G1+G2 7=G2+G3 8=G1 9=G3
__device__ float2 g_Wp[10][(D / 2) * D];

// ---------------- small setup kernels ----------------
__global__ void k_count(const int* __restrict__ edge_index,
                        const int* __restrict__ cat, int N, int E) {
    int i = blockIdx.x * blockDim.x + threadIdx.x;
    if (i < E) atomicAdd(&g_deg[edge_index[E + i]], 1);  // dst row
    if (i < N) atomicAdd(&g_bcnt[cat[i]], 1);
}

__global__ void k_scan(int N) {
    __shared__ int ssum[1024];
    int t = threadIdx.x;
    int C = (N + 1023) / 1024;
    int start = t * C;
    int end = min(start + C, N);
    int s = 0;
    for (int i = start; i < end; i++) s += g_deg[i];
    ssum[t] = s;
    __syncthreads();
    for (int off = 1; off < 1024; off <<= 1) {
        int v = 0;
        if (t >= off) v = ssum[t - off];
        __syncthreads();
        ssum[t] += v;
        __syncthreads();
    }
    int run = (t > 0) ? ssum[t - 1] : 0;
    for (int i = start; i < end; i++) {
        g_csroff[i] = run;
        g_cursor[i] = run;
        run += g_deg[i];
    }
    if (t == 1023) g_csroff[N] = ssum[1023];
    if (t == 0) {
        int c0 = g_bcnt[0], c1 = g_bcnt[1];
        g_boff[0] = 0; g_boff[1] = c0; g_boff[2] = c0 + c1; g_boff[3] = N;
        g_bcur[0] = 0; g_bcur[1] = c0; g_bcur[2] = c0 + c1;
    }
}

__global__ void k_scatter(const int* __restrict__ edge_index,
                          const int* __restrict__ cat, int N, int E) {
    int i = blockIdx.x * blockDim.x + threadIdx.x;
    if (i < E) {
        int d = edge_index[E + i];
        int p = atomicAdd(&g_cursor[d], 1);
        g_eid[p] = i;
    }
    if (i < N) {
        int p = atomicAdd(&g_bcur[cat[i]], 1);
        g_perm[p] = i;
    }
}

// pack all node-stage weight matrices into paired-k float2 layout
__global__ void k_prep(const float* __restrict__ Wr0,
                       const float* __restrict__ Wr1,
                       const float* __restrict__ Wr2,
                       const float* __restrict__ Wg,
                       const float* __restrict__ Wagg) {
    int idx = blockIdx.x * blockDim.x + threadIdx.x;
    const int PM = (D / 2) * D;                 // 8192 entries per matrix
    if (idx >= 10 * PM) return;
    int m = idx / PM;
    int r = (idx - m * PM) / D;                 // pair row (k = 2r, 2r+1)
    int c = idx - m * PM - r * D;               // output column
    float lo, hi;
    int k0 = 2 * r, k1 = 2 * r + 1;
    switch (m) {
        case 0: lo = Wr0[k0 * D + c];           hi = Wr0[k1 * D + c];           break;
        case 1: lo = Wr1[k0 * D + c];           hi = Wr1[k1 * D + c];           break;
        case 2: lo = Wr2[k0 * D + c];           hi = Wr2[k1 * D + c];           break;
        case 3: lo = Wg[k0 * D + c];            hi = Wg[k1 * D + c];            break;
        case 4: lo = Wg[(D + k0) * D + c];      hi = Wg[(D + k1) * D + c];      break;
        case 5: lo = Wagg[k0 * D + c];          hi = Wagg[k1 * D + c];          break;
        case 6: lo = Wagg[(D + k0) * D + c] + Wagg[(2 * D + k0) * D + c];
                hi = Wagg[(D + k1) * D + c] + Wagg[(2 * D + k1) * D + c];       break;
        case 7: lo = Wagg[(2 * D + k0) * D + c] + Wagg[(3 * D + k0) * D + c];
                hi = Wagg[(2 * D + k1) * D + c] + Wagg[(3 * D + k1) * D + c];   break;
        case 8: lo = Wagg[(D + k0) * D + c];    hi = Wagg[(D + k1) * D + c];    break;
        default: lo = Wagg[(3 * D + k0) * D + c]; hi = Wagg[(3 * D + k1) * D + c]; break;
    }
    g_Wp[m][r * D + c] = make_float2(lo, hi);
}

// ---------------- edge kernel: warp per node, online softmax ----------------
__global__ __launch_bounds__(256) void k_edge(
    const float* __restrict__ x, const int* __restrict__ edge_index,
    const int* __restrict__ ew_arr, const int* __restrict__ cat,
    const float* __restrict__ emb0, const float* __restrict__ emb1,
    const float* __restrict__ emb2,
    const float* __restrict__ Wa0, const float* __restrict__ Wa1,
    const float* __restrict__ Wa2,
    const float* __restrict__ ba0, const float* __restrict__ ba1,
    const float* __restrict__ ba2, int N) {
    __shared__ __align__(16) float semb[3 * 10 * D];
    __shared__ __align__(16) float swa1[3 * D];
    __shared__ __align__(16) float swa2[3 * D];
    __shared__ float sba[3];
    int tid = threadIdx.x;
    for (int q = tid; q < 3 * 10 * D; q += 256) {
        int c = q / (10 * D); int j = q - c * (10 * D);
        const float* p = (c == 0) ? emb0 : (c == 1 ? emb1 : emb2);
        semb[q] = p[j];
    }
    for (int q = tid; q < 3 * D; q += 256) {
        int c = q / D; int j = q - c * D;
        const float* p = (c == 0) ? Wa0 : (c == 1 ? Wa1 : Wa2);
        swa1[q] = p[j];
        swa2[q] = p[D + j];
    }
    if (tid < 3) sba[tid] = (tid == 0 ? ba0[0] : (tid == 1 ? ba1[0] : ba2[0]));
    __syncthreads();

    int warp = tid >> 5, lane = tid & 31;
    int node = blockIdx.x * 8 + warp;
    if (node >= N) return;
    int c = cat[node];
    const float4* x4 = (const float4*)x;
    float4 xn = x4[node * 32 + lane];
    float4 w1 = *(const float4*)&swa1[c * D + lane * 4];
    float p = xn.x * w1.x + xn.y * w1.y + xn.z * w1.z + xn.w * w1.w;
    p += __shfl_xor_sync(0xffffffffu, p, 16);
    p += __shfl_xor_sync(0xffffffffu, p, 8);
    p += __shfl_xor_sync(0xffffffffu, p, 4);
    p += __shfl_xor_sync(0xffffffffu, p, 2);
    p += __shfl_xor_sync(0xffffffffu, p, 1);
    float d1 = p + sba[c];
    float4 w2 = *(const float4*)&swa2[c * D + lane * 4];

    int beg = g_csroff[node], end = g_csroff[node + 1];
    float m = -1e30f, l = 0.f;
    float4 acc = make_float4(0.f, 0.f, 0.f, 0.f);
    for (int base = beg; base < end; base += 32) {
        int cnt = min(32, end - base);
        int myS = 0, myW = 0;
        if (lane < cnt) {
            int e = g_eid[base + lane];
            myS = edge_index[e];      // src row
            myW = ew_arr[e];
        }
        for (int t = 0; t < cnt; t++) {
            int s  = __shfl_sync(0xffffffffu, myS, t);
            int ew = __shfl_sync(0xffffffffu, myW, t);
            float4 xs = x4[s * 32 + lane];
            float4 em = *(const float4*)&semb[((c * 10 + ew) * D) + lane * 4];
            float4 nm = make_float4(em.x * xs.x, em.y * xs.y, em.z * xs.z, em.w * xs.w);
            float sc = nm.x * w2.x + nm.y * w2.y + nm.z * w2.z + nm.w * w2.w;
            sc += __shfl_xor_sync(0xffffffffu, sc, 16);
            sc += __shfl_xor_sync(0xffffffffu, sc, 8);
            sc += __shfl_xor_sync(0xffffffffu, sc, 4);
            sc += __shfl_xor_sync(0xffffffffu, sc, 2);
            sc += __shfl_xor_sync(0xffffffffu, sc, 1);
            sc += d1;
            sc = (sc >= 0.f) ? sc : -0.1f * sc;   // leaky_relu, slope -0.1
            float mn = fmaxf(m, sc);
            float scale = __expf(m - mn);
            float pe = __expf(sc - mn);
            l = l * scale + pe;
            acc.x = acc.x * scale + pe * nm.x;
            acc.y = acc.y * scale + pe * nm.y;
            acc.z = acc.z * scale + pe * nm.z;
            acc.w = acc.w * scale + pe * nm.w;
            m = mn;
        }
    }
    float4 hv = make_float4(0.f, 0.f, 0.f, 0.f);
    if (end > beg) {
        float inv = 1.0f / fmaxf(l, 1e-16f);
        hv = make_float4(acc.x * inv, acc.y * inv, acc.z * inv, acc.w * inv);
    }
    ((float4*)g_h)[node * 32 + lane] = hv;
}

// ---------------- node kernel: 16-node tiles, 2 smem buffers, high occupancy ----
#define TN 16   // nodes per tile

__device__ __forceinline__ void gemm16(float* acc, const float2* __restrict__ Wp,
                                       const float* sIn, int tid, bool zero) {
    if (zero) {
        #pragma unroll
        for (int i = 0; i < TN; i++) acc[i] = 0.f;
    }
    float2 w0 = Wp[tid];
    float2 w1 = Wp[D + tid];
    #pragma unroll 1
    for (int kp = 0; kp < D / 2; kp += 2) {     // 4 k-values per iteration
        float2 a0 = w0, a1 = w1;
        if (kp + 2 < D / 2) {                   // prefetch next chunk's weights
            w0 = Wp[(kp + 2) * D + tid];
            w1 = Wp[(kp + 3) * D + tid];
        }
        const float4* in4 = (const float4*)(sIn + kp * 2);
        #pragma unroll
        for (int i = 0; i < TN; i++) {
            float4 v = in4[i * 32];             // broadcast LDS.128
            float a = acc[i];
            a = fmaf(v.x, a0.x, a);
            a = fmaf(v.y, a0.y, a);
            a = fmaf(v.z, a1.x, a);
            a = fmaf(v.w, a1.y, a);
            acc[i] = a;
        }
    }
}

__global__ __launch_bounds__(128, 8) void k_node(
    const float* __restrict__ x,
    const float* __restrict__ br0, const float* __restrict__ br1,
    const float* __restrict__ br2,
    const float* __restrict__ bgate, const float* __restrict__ bagg,
    float* __restrict__ out, int N, int Tt) {
    __shared__ __align__(16) float sP[TN * D];  // x, later u (or u3)
    __shared__ __align__(16) float sQ[TN * D];  // h, later A (or u1)
    int tid = threadIdx.x;
    int c = blockIdx.x / Tt;
    int t = blockIdx.x - c * Tt;
    int r0 = g_boff[c] + t * TN;
    int r1 = min(g_boff[c + 1], r0 + TN);
    if (r0 >= r1) return;
    int nn = r1 - r0;

    const float4* x4g = (const float4*)x;
    const float4* h4g = (const float4*)g_h;
    float4* sP4 = (float4*)sP;
    float4* sQ4 = (float4*)sQ;
    for (int q = tid; q < TN * 32; q += 128) {
        int i = q >> 5, v = q & 31;
        float4 xv = make_float4(0.f, 0.f, 0.f, 0.f);
        float4 hv = make_float4(0.f, 0.f, 0.f, 0.f);
        if (i < nn) {
            int node = g_perm[r0 + i];
            xv = x4g[node * 32 + v];
            hv = h4g[node * 32 + v];
        }
        sP4[q] = xv;
        sQ4[q] = hv;
    }
    __syncthreads();

    float accA[TN], accB[TN];
    const float* br = (c == 0) ? br0 : (c == 1 ? br1 : br2);
    gemm16(accA, g_Wp[c], sQ, tid, true);       // A = h @ W_r_c
    __syncthreads();                            // all warps done reading sQ(h)
    {
        float b = br[tid];
        #pragma unroll
        for (int i = 0; i < TN; i++) {
            float fl = 0.f;
            if (i < nn) fl = (g_deg[g_perm[r0 + i]] > 0) ? 1.f : 0.f;
            sQ[i * D + tid] = accA[i] + b * fl; // sQ = A
        }
    }
    __syncthreads();

    float bg = bgate[tid];
    gemm16(accB, g_Wp[5], sP, tid, true);       // running total: G0 @ x
    if (c == 0) {
        // contrib += ((1-sigmoid(A@WgT+bg)) * A) @ (G1+G2)
        gemm16(accA, g_Wp[3], sQ, tid, true);   // WgT @ A
        __syncthreads();                        // G0@sP done by all warps
        #pragma unroll
        for (int i = 0; i < TN; i++) {
            float g = 1.f / (1.f + __expf(-(accA[i] + bg)));
            sP[i * D + tid] = (1.f - g) * sQ[i * D + tid];
        }
        __syncthreads();
        gemm16(accB, g_Wp[6], sP, tid, false);  // += (G1+G2) @ u
    } else if (c == 2) {
        // contrib += (sigmoid(A@WgB+bg) * A) @ (G2+G3)
        gemm16(accA, g_Wp[4], sQ, tid, true);   // WgB @ A
        __syncthreads();
        #pragma unroll
        for (int i = 0; i < TN; i++) {
            float g = 1.f / (1.f + __expf(-(accA[i] + bg)));
            sP[i * D + tid] = g * sQ[i * D + tid];
        }
        __syncthreads();
        gemm16(accB, g_Wp[7], sP, tid, false);  // += (G2+G3) @ u
    } else {
        // contrib += u1@G1 + u3@G3, u1 = sigmoid(A@WgB)*A, u3 = (1-sigmoid(A@WgT))*A
        gemm16(accA, g_Wp[3], sQ, tid, true);   // WgT @ A
        __syncthreads();                        // G0@sP done by all warps
        #pragma unroll
        for (int i = 0; i < TN; i++) {
            float g = 1.f / (1.f + __expf(-(accA[i] + bg)));
            sP[i * D + tid] = (1.f - g) * sQ[i * D + tid];   // u3
        }
        gemm16(accA, g_Wp[4], sQ, tid, true);   // WgB @ A (sQ unchanged; sP write no conflict)
        __syncthreads();                        // all sP writes + all WgB@sQ reads done
        #pragma unroll
        for (int i = 0; i < TN; i++) {
            float g = 1.f / (1.f + __expf(-(accA[i] + bg)));
            sQ[i * D + tid] = g * sQ[i * D + tid];           // u1 (own-element RMW)
        }
        __syncthreads();
        gemm16(accB, g_Wp[9], sP, tid, false);  // += G3 @ u3
        gemm16(accB, g_Wp[8], sQ, tid, false);  // += G1 @ u1
    }
    float ba = bagg[tid];
    #pragma unroll 1
    for (int i = 0; i < nn; i++) {
        out[(size_t)g_perm[r0 + i] * D + tid] = tanhf(accB[i] + ba);
    }
}

// zero output remainder + reset scratch counters for the next graph replay
__global__ void k_tail(float* out, long nd, long total, int N) {
    long i = (long)blockIdx.x * blockDim.x + threadIdx.x;
    if (nd + i < total) out[nd + i] = 0.f;
    if (i < N) g_deg[i] = 0;
    if (i < 3) g_bcnt[i] = 0;
}

// ---------------- launch ----------------
extern "C" void kernel_launch(void* const* d_in, const int* in_sizes, int n_in,
                              void* d_out, int out_size) {
    const float* x          = (const float*)d_in[0];
    const int*   edge_index = (const int*)d_in[1];
    const int*   edge_weight= (const int*)d_in[2];
    const int*   cat        = (const int*)d_in[3];
    const float* Wr0 = (const float*)d_in[4];
    const float* br0 = (const float*)d_in[5];
    const float* Wa0 = (const float*)d_in[6];
    const float* ba0 = (const float*)d_in[7];
    const float* em0 = (const float*)d_in[8];
    const float* Wr1 = (const float*)d_in[9];
    const float* br1 = (const float*)d_in[10];
    const float* Wa1 = (const float*)d_in[11];
    const float* ba1 = (const float*)d_in[12];
    const float* em1 = (const float*)d_in[13];
    const float* Wr2 = (const float*)d_in[14];
    const float* br2 = (const float*)d_in[15];
    const float* Wa2 = (const float*)d_in[16];
    const float* ba2 = (const float*)d_in[17];
    const float* em2 = (const float*)d_in[18];
    const float* Wg  = (const float*)d_in[19];
    const float* bg  = (const float*)d_in[20];
    const float* Wagg= (const float*)d_in[21];
    const float* bagg= (const float*)d_in[22];
    float* out = (float*)d_out;

    int N = in_sizes[0] / D;
    int E = in_sizes[2];
    int M = (E > N) ? E : N;

    // order chosen so the ncu window (lands on our 4th launch) captures k_edge
    k_count<<<(M + 255) / 256, 256>>>(edge_index, cat, N, E);
    k_scan<<<1, 1024>>>(N);
    k_scatter<<<(M + 255) / 256, 256>>>(edge_index, cat, N, E);
    k_edge<<<(N + 7) / 8, 256>>>(x, edge_index, edge_weight, cat,
                                 em0, em1, em2, Wa0, Wa1, Wa2,
                                 ba0, ba1, ba2, N);
    k_prep<<<(10 * (D / 2) * D + 255) / 256, 256>>>(Wr0, Wr1, Wr2, Wg, Wagg);
    int Tt = (N + TN - 1) / TN;
    k_node<<<3 * Tt, 128>>>(x, br0, br1, br2, bg, bagg, out, N, Tt);
    long nd = (long)N * D;
    long rem = (long)out_size - nd;
    long cover = (rem > (long)N) ? rem : (long)N;
    k_tail<<<(int)((cover + 255) / 256), 256>>>(out, nd, (long)out_size, N);
}

// round 9
// speedup vs baseline: 1.0036x; 1.0036x over previous
#include <cuda_runtime.h>
#include <math.h>

#define D 128
#define MAXN 50000
#define MAXE 400000

// ---------------- scratch (static __device__, no allocation) ----------------
// __device__ globals are zero-initialized at module load; k_tail re-zeros
// g_deg/g_bcnt at the end of every call so each graph replay sees clean state.
__device__ float g_h[MAXN * D];          // per-node attention-weighted message
__device__ int   g_deg[MAXN];
__device__ int   g_csroff[MAXN + 1];
__device__ int   g_cursor[MAXN];
__device__ int   g_eid[MAXE];
__device__ int   g_perm[MAXN];           // nodes sorted by cat
__device__ int   g_bcnt[3];
__device__ int   g_boff[4];
__device__ int   g_bcur[3];
// packed weight matrices: pair-of-k-rows layout, Wp[m][kp*D + c] = (W[2kp][c], W[2kp+1][c])
// m: 0=Wr0 1=Wr1 2=Wr2 3=WgTop 4=WgBot 5=G0 6=G1+G2 7=G2+G3 8=G1 9=G3
__device__ float2 g_Wp[10][(D / 2) * D];

// ---------------- small setup kernels ----------------
__global__ void k_count(const int* __restrict__ edge_index,
                        const int* __restrict__ cat, int N, int E) {
    int i = blockIdx.x * blockDim.x + threadIdx.x;
    if (i < E) atomicAdd(&g_deg[edge_index[E + i]], 1);  // dst row
    if (i < N) atomicAdd(&g_bcnt[cat[i]], 1);
}

__global__ void k_scan(int N) {
    __shared__ int ssum[1024];
    int t = threadIdx.x;
    int C = (N + 1023) / 1024;
    int start = t * C;
    int end = min(start + C, N);
    int s = 0;
    for (int i = start; i < end; i++) s += g_deg[i];
    ssum[t] = s;
    __syncthreads();
    for (int off = 1; off < 1024; off <<= 1) {
        int v = 0;
        if (t >= off) v = ssum[t - off];
        __syncthreads();
        ssum[t] += v;
        __syncthreads();
    }
    int run = (t > 0) ? ssum[t - 1] : 0;
    for (int i = start; i < end; i++) {
        g_csroff[i] = run;
        g_cursor[i] = run;
        run += g_deg[i];
    }
    if (t == 1023) g_csroff[N] = ssum[1023];
    if (t == 0) {
        int c0 = g_bcnt[0], c1 = g_bcnt[1];
        g_boff[0] = 0; g_boff[1] = c0; g_boff[2] = c0 + c1; g_boff[3] = N;
        g_bcur[0] = 0; g_bcur[1] = c0; g_bcur[2] = c0 + c1;
    }
}

__global__ void k_scatter(const int* __restrict__ edge_index,
                          const int* __restrict__ cat, int N, int E) {
    int i = blockIdx.x * blockDim.x + threadIdx.x;
    if (i < E) {
        int d = edge_index[E + i];
        int p = atomicAdd(&g_cursor[d], 1);
        g_eid[p] = i;
    }
    if (i < N) {
        int p = atomicAdd(&g_bcur[cat[i]], 1);
        g_perm[p] = i;
    }
}

// pack all node-stage weight matrices into paired-k float2 layout
__global__ void k_prep(const float* __restrict__ Wr0,
                       const float* __restrict__ Wr1,
                       const float* __restrict__ Wr2,
                       const float* __restrict__ Wg,
                       const float* __restrict__ Wagg) {
    int idx = blockIdx.x * blockDim.x + threadIdx.x;
    const int PM = (D / 2) * D;                 // 8192 entries per matrix
    if (idx >= 10 * PM) return;
    int m = idx / PM;
    int r = (idx - m * PM) / D;                 // pair row (k = 2r, 2r+1)
    int c = idx - m * PM - r * D;               // output column
    float lo, hi;
    int k0 = 2 * r, k1 = 2 * r + 1;
    switch (m) {
        case 0: lo = Wr0[k0 * D + c];           hi = Wr0[k1 * D + c];           break;
        case 1: lo = Wr1[k0 * D + c];           hi = Wr1[k1 * D + c];           break;
        case 2: lo = Wr2[k0 * D + c];           hi = Wr2[k1 * D + c];           break;
        case 3: lo = Wg[k0 * D + c];            hi = Wg[k1 * D + c];            break;
        case 4: lo = Wg[(D + k0) * D + c];      hi = Wg[(D + k1) * D + c];      break;
        case 5: lo = Wagg[k0 * D + c];          hi = Wagg[k1 * D + c];          break;
        case 6: lo = Wagg[(D + k0) * D + c] + Wagg[(2 * D + k0) * D + c];
                hi = Wagg[(D + k1) * D + c] + Wagg[(2 * D + k1) * D + c];       break;
        case 7: lo = Wagg[(2 * D + k0) * D + c] + Wagg[(3 * D + k0) * D + c];
                hi = Wagg[(2 * D + k1) * D + c] + Wagg[(3 * D + k1) * D + c];   break;
        case 8: lo = Wagg[(D + k0) * D + c];    hi = Wagg[(D + k1) * D + c];    break;
        default: lo = Wagg[(3 * D + k0) * D + c]; hi = Wagg[(3 * D + k1) * D + c]; break;
    }
    g_Wp[m][r * D + c] = make_float2(lo, hi);
}

// ---------------- edge kernel: warp per node, online softmax ----------------
__global__ __launch_bounds__(256) void k_edge(
    const float* __restrict__ x, const int* __restrict__ edge_index,
    const int* __restrict__ ew_arr, const int* __restrict__ cat,
    const float* __restrict__ emb0, const float* __restrict__ emb1,
    const float* __restrict__ emb2,
    const float* __restrict__ Wa0, const float* __restrict__ Wa1,
    const float* __restrict__ Wa2,
    const float* __restrict__ ba0, const float* __restrict__ ba1,
    const float* __restrict__ ba2, int N) {
    __shared__ __align__(16) float semb[3 * 10 * D];
    __shared__ __align__(16) float swa1[3 * D];
    __shared__ __align__(16) float swa2[3 * D];
    __shared__ float sba[3];
    int tid = threadIdx.x;
    for (int q = tid; q < 3 * 10 * D; q += 256) {
        int c = q / (10 * D); int j = q - c * (10 * D);
        const float* p = (c == 0) ? emb0 : (c == 1 ? emb1 : emb2);
        semb[q] = p[j];
    }
    for (int q = tid; q < 3 * D; q += 256) {
        int c = q / D; int j = q - c * D;
        const float* p = (c == 0) ? Wa0 : (c == 1 ? Wa1 : Wa2);
        swa1[q] = p[j];
        swa2[q] = p[D + j];
    }
    if (tid < 3) sba[tid] = (tid == 0 ? ba0[0] : (tid == 1 ? ba1[0] : ba2[0]));
    __syncthreads();

    int warp = tid >> 5, lane = tid & 31;
    int node = blockIdx.x * 8 + warp;
    if (node >= N) return;
    int c = cat[node];
    const float4* x4 = (const float4*)x;
    float4 xn = x4[node * 32 + lane];
    float4 w1 = *(const float4*)&swa1[c * D + lane * 4];
    float p = xn.x * w1.x + xn.y * w1.y + xn.z * w1.z + xn.w * w1.w;
    p += __shfl_xor_sync(0xffffffffu, p, 16);
    p += __shfl_xor_sync(0xffffffffu, p, 8);
    p += __shfl_xor_sync(0xffffffffu, p, 4);
    p += __shfl_xor_sync(0xffffffffu, p, 2);
    p += __shfl_xor_sync(0xffffffffu, p, 1);
    float d1 = p + sba[c];
    float4 w2 = *(const float4*)&swa2[c * D + lane * 4];

    int beg = g_csroff[node], end = g_csroff[node + 1];
    float m = -1e30f, l = 0.f;
    float4 acc = make_float4(0.f, 0.f, 0.f, 0.f);
    for (int base = beg; base < end; base += 32) {
        int cnt = min(32, end - base);
        int myS = 0, myW = 0;
        if (lane < cnt) {
            int e = g_eid[base + lane];
            myS = edge_index[e];      // src row
            myW = ew_arr[e];
        }
        for (int t = 0; t < cnt; t++) {
            int s  = __shfl_sync(0xffffffffu, myS, t);
            int ew = __shfl_sync(0xffffffffu, myW, t);
            float4 xs = x4[s * 32 + lane];
            float4 em = *(const float4*)&semb[((c * 10 + ew) * D) + lane * 4];
            float4 nm = make_float4(em.x * xs.x, em.y * xs.y, em.z * xs.z, em.w * xs.w);
            float sc = nm.x * w2.x + nm.y * w2.y + nm.z * w2.z + nm.w * w2.w;
            sc += __shfl_xor_sync(0xffffffffu, sc, 16);
            sc += __shfl_xor_sync(0xffffffffu, sc, 8);
            sc += __shfl_xor_sync(0xffffffffu, sc, 4);
            sc += __shfl_xor_sync(0xffffffffu, sc, 2);
            sc += __shfl_xor_sync(0xffffffffu, sc, 1);
            sc += d1;
            sc = (sc >= 0.f) ? sc : -0.1f * sc;   // leaky_relu, slope -0.1
            float mn = fmaxf(m, sc);
            float scale = __expf(m - mn);
            float pe = __expf(sc - mn);
            l = l * scale + pe;
            acc.x = acc.x * scale + pe * nm.x;
            acc.y = acc.y * scale + pe * nm.y;
            acc.z = acc.z * scale + pe * nm.z;
            acc.w = acc.w * scale + pe * nm.w;
            m = mn;
        }
    }
    float4 hv = make_float4(0.f, 0.f, 0.f, 0.f);
    if (end > beg) {
        float inv = 1.0f / fmaxf(l, 1e-16f);
        hv = make_float4(acc.x * inv, acc.y * inv, acc.z * inv, acc.w * inv);
    }
    ((float4*)g_h)[node * 32 + lane] = hv;
}

// ---------------- node kernel: 16-node tiles, 2 smem buffers, high occupancy ----
#define TN 16   // nodes per tile

__device__ __forceinline__ void gemm16(float* acc, const float2* __restrict__ Wp,
                                       const float* sIn, int tid, bool zero) {
    if (zero) {
        #pragma unroll
        for (int i = 0; i < TN; i++) acc[i] = 0.f;
    }
    float2 w0 = Wp[tid];
    float2 w1 = Wp[D + tid];
    #pragma unroll 1
    for (int kp = 0; kp < D / 2; kp += 2) {     // 4 k-values per iteration
        float2 a0 = w0, a1 = w1;
        if (kp + 2 < D / 2) {                   // prefetch next chunk's weights
            w0 = Wp[(kp + 2) * D + tid];
            w1 = Wp[(kp + 3) * D + tid];
        }
        const float4* in4 = (const float4*)(sIn + kp * 2);
        #pragma unroll
        for (int i = 0; i < TN; i++) {
            float4 v = in4[i * 32];             // broadcast LDS.128
            float a = acc[i];
            a = fmaf(v.x, a0.x, a);
            a = fmaf(v.y, a0.y, a);
            a = fmaf(v.z, a1.x, a);
            a = fmaf(v.w, a1.y, a);
            acc[i] = a;
        }
    }
}

__global__ __launch_bounds__(128, 8) void k_node(
    const float* __restrict__ x,
    const float* __restrict__ br0, const float* __restrict__ br1,
    const float* __restrict__ br2,
    const float* __restrict__ bgate, const float* __restrict__ bagg,
    float* __restrict__ out, int N, int Tt) {
    __shared__ __align__(16) float sP[TN * D];  // x, later u (or u3)
    __shared__ __align__(16) float sQ[TN * D];  // h, later A (or u1)
    int tid = threadIdx.x;
    int c = blockIdx.x / Tt;
    int t = blockIdx.x - c * Tt;
    int r0 = g_boff[c] + t * TN;
    int r1 = min(g_boff[c + 1], r0 + TN);
    if (r0 >= r1) return;
    int nn = r1 - r0;

    const float4* x4g = (const float4*)x;
    const float4* h4g = (const float4*)g_h;
    float4* sP4 = (float4*)sP;
    float4* sQ4 = (float4*)sQ;
    for (int q = tid; q < TN * 32; q += 128) {
        int i = q >> 5, v = q & 31;
        float4 xv = make_float4(0.f, 0.f, 0.f, 0.f);
        float4 hv = make_float4(0.f, 0.f, 0.f, 0.f);
        if (i < nn) {
            int node = g_perm[r0 + i];
            xv = x4g[node * 32 + v];
            hv = h4g[node * 32 + v];
        }
        sP4[q] = xv;
        sQ4[q] = hv;
    }
    __syncthreads();

    float accA[TN], accB[TN];
    const float* br = (c == 0) ? br0 : (c == 1 ? br1 : br2);
    gemm16(accA, g_Wp[c], sQ, tid, true);       // A = h @ W_r_c
    __syncthreads();                            // all warps done reading sQ(h)
    {
        float b = br[tid];
        #pragma unroll
        for (int i = 0; i < TN; i++) {
            float fl = 0.f;
            if (i < nn) fl = (g_deg[g_perm[r0 + i]] > 0) ? 1.f : 0.f;
            sQ[i * D + tid] = accA[i] + b * fl; // sQ = A
        }
    }
    __syncthreads();

    float bg = bgate[tid];
    gemm16(accB, g_Wp[5], sP, tid, true);       // running total: G0 @ x
    if (c == 0) {
        // contrib += ((1-sigmoid(A@WgT+bg)) * A) @ (G1+G2)
        gemm16(accA, g_Wp[3], sQ, tid, true);   // WgT @ A
        __syncthreads();                        // G0@sP done by all warps
        #pragma unroll
        for (int i = 0; i < TN; i++) {
            float g = 1.f / (1.f + __expf(-(accA[i] + bg)));
            sP[i * D + tid] = (1.f - g) * sQ[i * D + tid];
        }
        __syncthreads();
        gemm16(accB, g_Wp[6], sP, tid, false);  // += (G1+G2) @ u
    } else if (c == 2) {
        // contrib += (sigmoid(A@WgB+bg) * A) @ (G2+G3)
        gemm16(accA, g_Wp[4], sQ, tid, true);   // WgB @ A
        __syncthreads();
        #pragma unroll
        for (int i = 0; i < TN; i++) {
            float g = 1.f / (1.f + __expf(-(accA[i] + bg)));
            sP[i * D + tid] = g * sQ[i * D + tid];
        }
        __syncthreads();
        gemm16(accB, g_Wp[7], sP, tid, false);  // += (G2+G3) @ u
    } else {
        // contrib += u1@G1 + u3@G3, u1 = sigmoid(A@WgB)*A, u3 = (1-sigmoid(A@WgT))*A
        gemm16(accA, g_Wp[3], sQ, tid, true);   // WgT @ A
        __syncthreads();                        // G0@sP done by all warps
        #pragma unroll
        for (int i = 0; i < TN; i++) {
            float g = 1.f / (1.f + __expf(-(accA[i] + bg)));
            sP[i * D + tid] = (1.f - g) * sQ[i * D + tid];   // u3
        }
        gemm16(accA, g_Wp[4], sQ, tid, true);   // WgB @ A (sQ unchanged; sP write no conflict)
        __syncthreads();                        // all sP writes + all WgB@sQ reads done
        #pragma unroll
        for (int i = 0; i < TN; i++) {
            float g = 1.f / (1.f + __expf(-(accA[i] + bg)));
            sQ[i * D + tid] = g * sQ[i * D + tid];           // u1 (own-element RMW)
        }
        __syncthreads();
        gemm16(accB, g_Wp[9], sP, tid, false);  // += G3 @ u3
        gemm16(accB, g_Wp[8], sQ, tid, false);  // += G1 @ u1
    }
    float ba = bagg[tid];
    #pragma unroll 1
    for (int i = 0; i < nn; i++) {
        out[(size_t)g_perm[r0 + i] * D + tid] = tanhf(accB[i] + ba);
    }
}

// zero output remainder + reset scratch counters for the next graph replay
__global__ void k_tail(float* out, long nd, long total, int N) {
    long i = (long)blockIdx.x * blockDim.x + threadIdx.x;
    if (nd + i < total) out[nd + i] = 0.f;
    if (i < N) g_deg[i] = 0;
    if (i < 3) g_bcnt[i] = 0;
}

// ---------------- launch ----------------
extern "C" void kernel_launch(void* const* d_in, const int* in_sizes, int n_in,
                              void* d_out, int out_size) {
    const float* x          = (const float*)d_in[0];
    const int*   edge_index = (const int*)d_in[1];
    const int*   edge_weight= (const int*)d_in[2];
    const int*   cat        = (const int*)d_in[3];
    const float* Wr0 = (const float*)d_in[4];
    const float* br0 = (const float*)d_in[5];
    const float* Wa0 = (const float*)d_in[6];
    const float* ba0 = (const float*)d_in[7];
    const float* em0 = (const float*)d_in[8];
    const float* Wr1 = (const float*)d_in[9];
    const float* br1 = (const float*)d_in[10];
    const float* Wa1 = (const float*)d_in[11];
    const float* ba1 = (const float*)d_in[12];
    const float* em1 = (const float*)d_in[13];
    const float* Wr2 = (const float*)d_in[14];
    const float* br2 = (const float*)d_in[15];
    const float* Wa2 = (const float*)d_in[16];
    const float* ba2 = (const float*)d_in[17];
    const float* em2 = (const float*)d_in[18];
    const float* Wg  = (const float*)d_in[19];
    const float* bg  = (const float*)d_in[20];
    const float* Wagg= (const float*)d_in[21];
    const float* bagg= (const float*)d_in[22];
    float* out = (float*)d_out;

    int N = in_sizes[0] / D;
    int E = in_sizes[2];
    int M = (E > N) ? E : N;

    // order chosen so the ncu window (lands on our 4th launch) captures k_edge
    k_count<<<(M + 255) / 256, 256>>>(edge_index, cat, N, E);
    k_scan<<<1, 1024>>>(N);
    k_scatter<<<(M + 255) / 256, 256>>>(edge_index, cat, N, E);
    k_edge<<<(N + 7) / 8, 256>>>(x, edge_index, edge_weight, cat,
                                 em0, em1, em2, Wa0, Wa1, Wa2,
                                 ba0, ba1, ba2, N);
    k_prep<<<(10 * (D / 2) * D + 255) / 256, 256>>>(Wr0, Wr1, Wr2, Wg, Wagg);
    int Tt = (N + TN - 1) / TN;
    k_node<<<3 * Tt, 128>>>(x, br0, br1, br2, bg, bagg, out, N, Tt);
    long nd = (long)N * D;
    long rem = (long)out_size - nd;
    long cover = (rem > (long)N) ? rem : (long)N;
    k_tail<<<(int)((cover + 255) / 256), 256>>>(out, nd, (long)out_size, N);
}